// round 1
// baseline (speedup 1.0000x reference)
#include <cuda_runtime.h>

#define N_NODES 8192
#define D_IN    256
#define H_DIM   64
#define DEG     32
#define E_EDGES (N_NODES * DEG)

// Scratch for projected Q, K, V  (8192 x 64 floats each = 2 MB each)
__device__ float g_Q[N_NODES * H_DIM];
__device__ float g_K[N_NODES * H_DIM];
__device__ float g_V[N_NODES * H_DIM];

// ---------------------------------------------------------------------------
// Kernel 1: fused QKV projection.
//   C[8192, 192] = x[8192,256] @ [Wq;Wk;Wv]^T (+ bias for Q,K cols)
// Block tile: 64 rows x 192 cols, BK=16. 256 threads, microtile 4x12.
// ---------------------------------------------------------------------------
__global__ __launch_bounds__(256) void qkv_kernel(
    const float* __restrict__ x,
    const float* __restrict__ Wq, const float* __restrict__ bq,
    const float* __restrict__ Wk, const float* __restrict__ bk,
    const float* __restrict__ Wv)
{
    __shared__ __align__(16) float xs[16][68];   // [k][row]  (transposed x tile)
    __shared__ __align__(16) float ws[16][194];  // [k][col]  (transposed W tile)

    const int tid = threadIdx.x;
    const int tx  = tid & 15;       // 0..15 -> column group
    const int ty  = tid >> 4;       // 0..15 -> row group
    const int r0  = blockIdx.x * 64;

    float acc[4][12];
    #pragma unroll
    for (int i = 0; i < 4; i++)
        #pragma unroll
        for (int s = 0; s < 12; s++) acc[i][s] = 0.f;

    for (int kk = 0; kk < D_IN; kk += 16) {
        // --- load x tile: 64 rows x 16 k, one float4 per thread ---
        {
            int row = tid >> 2;          // 0..63
            int seg = tid & 3;           // 0..3 (which float4 in k-direction)
            float4 v = *(const float4*)&x[(r0 + row) * D_IN + kk + seg * 4];
            xs[seg * 4 + 0][row] = v.x;
            xs[seg * 4 + 1][row] = v.y;
            xs[seg * 4 + 2][row] = v.z;
            xs[seg * 4 + 3][row] = v.w;
        }
        // --- load W tile: 192 cols x 16 k (768 float4, 3 per thread) ---
        #pragma unroll
        for (int t = 0; t < 3; t++) {
            int idx = tid + t * 256;     // 0..767
            int c   = idx >> 2;          // 0..191
            int seg = idx & 3;           // 0..3
            const float* Wsrc = (c < 64)  ? &Wq[c * D_IN]
                              : (c < 128) ? &Wk[(c - 64) * D_IN]
                                          : &Wv[(c - 128) * D_IN];
            float4 v = *(const float4*)&Wsrc[kk + seg * 4];
            ws[seg * 4 + 0][c] = v.x;
            ws[seg * 4 + 1][c] = v.y;
            ws[seg * 4 + 2][c] = v.z;
            ws[seg * 4 + 3][c] = v.w;
        }
        __syncthreads();

        #pragma unroll
        for (int k = 0; k < 16; k++) {
            float4 xv4 = *(const float4*)&xs[k][ty * 4];
            float xv[4] = {xv4.x, xv4.y, xv4.z, xv4.w};
            float wv[12];
            #pragma unroll
            for (int s = 0; s < 12; s++) wv[s] = ws[k][tx + s * 16];
            #pragma unroll
            for (int i = 0; i < 4; i++)
                #pragma unroll
                for (int s = 0; s < 12; s++)
                    acc[i][s] += xv[i] * wv[s];
        }
        __syncthreads();
    }

    // --- epilogue: bias + scatter to g_Q / g_K / g_V ---
    #pragma unroll
    for (int s = 0; s < 12; s++) {
        int c = tx + s * 16;             // 0..191, uniform branch per warp per s
        float b;
        float* dst;
        int h;
        if (c < 64)        { b = bq[c];      dst = g_Q; h = c; }
        else if (c < 128)  { b = bk[c - 64]; dst = g_K; h = c - 64; }
        else               { b = 0.f;        dst = g_V; h = c - 128; }
        #pragma unroll
        for (int i = 0; i < 4; i++) {
            int row = r0 + ty * 4 + i;
            dst[row * H_DIM + h] = acc[i][s] + b;
        }
    }
}

// ---------------------------------------------------------------------------
// Kernel 2: sparse attention. One warp per node; lane l owns neighbor l.
//   s_l = (Q_i . K_{j_l} + ek_l) / 512 ; warp softmax ; out_i = sum p_l V_{j_l}
// ---------------------------------------------------------------------------
__global__ __launch_bounds__(256) void attn_kernel(
    const int*   __restrict__ edge_index,   // [2, E]: src then dst
    const int*   __restrict__ edge_type,    // [E]
    const float* __restrict__ ek_table,     // [16]
    float*       __restrict__ out)          // [N, 64]
{
    const int gwarp = (blockIdx.x * blockDim.x + threadIdx.x) >> 5;
    const int lane  = threadIdx.x & 31;
    if (gwarp >= N_NODES) return;
    const int i = gwarp;
    const int e = i * DEG + lane;

    const int   j  = edge_index[E_EDGES + e];     // dst neighbor of node i
    const float ek = ek_table[edge_type[e]];

    // dot(Q_i, K_j): Q_i loads are warp-uniform (L1 broadcast)
    const float4* Kj = (const float4*)&g_K[j * H_DIM];
    const float4* Qi = (const float4*)&g_Q[i * H_DIM];
    float s = 0.f;
    #pragma unroll
    for (int d4 = 0; d4 < H_DIM / 4; d4++) {
        float4 q = Qi[d4];
        float4 k = Kj[d4];
        s += q.x * k.x + q.y * k.y + q.z * k.z + q.w * k.w;
    }
    s = (s + ek) * (1.0f / 512.0f);   // (/H) then (/sqrt(H)) = /512

    // warp softmax over the 32 neighbor scores
    float m = s;
    #pragma unroll
    for (int o = 16; o > 0; o >>= 1) m = fmaxf(m, __shfl_xor_sync(0xffffffffu, m, o));
    float p = __expf(s - m);
    float sum = p;
    #pragma unroll
    for (int o = 16; o > 0; o >>= 1) sum += __shfl_xor_sync(0xffffffffu, sum, o);
    p *= (1.0f / sum) * sum == 0.f ? 0.f : 1.0f / sum;  // placeholder guarded below

    // NOTE: the line above is replaced by a plain divide to stay exact:
    // (kept simple & correct)
    // p = e / sum  — recompute cleanly:
    p = __expf(s - m) / sum;

    // weighted V sum: lane owns output dims {2*lane, 2*lane+1}
    float a0 = 0.f, a1 = 0.f;
    #pragma unroll
    for (int n = 0; n < DEG; n++) {
        float pn = __shfl_sync(0xffffffffu, p, n);
        int   jn = __shfl_sync(0xffffffffu, j, n);
        float2 v = *(const float2*)&g_V[jn * H_DIM + lane * 2];
        a0 += pn * v.x;
        a1 += pn * v.y;
    }
    *(float2*)&out[i * H_DIM + lane * 2] = make_float2(a0, a1);
}

// ---------------------------------------------------------------------------
extern "C" void kernel_launch(void* const* d_in, const int* in_sizes, int n_in,
                              void* d_out, int out_size)
{
    const float* x          = (const float*)d_in[0];
    // d_in[1] = adj [8192*8192] — intentionally unused (edge list is exact)
    const int*   edge_index = (const int*)d_in[2];
    const int*   edge_type  = (const int*)d_in[3];
    const float* Wq         = (const float*)d_in[4];
    const float* bq         = (const float*)d_in[5];
    const float* Wk         = (const float*)d_in[6];
    const float* bk         = (const float*)d_in[7];
    const float* Wv         = (const float*)d_in[8];
    const float* ekt        = (const float*)d_in[9];
    float*       out        = (float*)d_out;

    qkv_kernel<<<N_NODES / 64, 256>>>(x, Wq, bq, Wk, bk, Wv);
    attn_kernel<<<(N_NODES * 32) / 256, 256>>>(edge_index, edge_type, ekt, out);
}

// round 2
// speedup vs baseline: 1.1637x; 1.1637x over previous
#include <cuda_runtime.h>

#define N_NODES 8192
#define D_IN    256
#define H_DIM   64
#define DEG     32
#define E_EDGES (N_NODES * DEG)

// Scratch for projected Q, K, V  (8192 x 64 floats each = 2 MB each)
__device__ float g_Q[N_NODES * H_DIM];
__device__ float g_K[N_NODES * H_DIM];
__device__ float g_V[N_NODES * H_DIM];

// ---------------------------------------------------------------------------
// Kernel 1: fused QKV projection.
//   C[8192, 192] = x[8192,256] @ [Wq;Wk;Wv]^T (+ bias for Q,K cols)
// Block tile: 64 rows x 192 cols, BK=16. 256 threads.
// Microtile 4 rows x 12 cols, cols owned as 3 float4 groups (vectorized LDS).
// ---------------------------------------------------------------------------
__global__ __launch_bounds__(256) void qkv_kernel(
    const float* __restrict__ x,
    const float* __restrict__ Wq, const float* __restrict__ bq,
    const float* __restrict__ Wk, const float* __restrict__ bk,
    const float* __restrict__ Wv)
{
    __shared__ __align__(16) float xs[16][68];    // [k][row]
    __shared__ __align__(16) float ws[16][196];   // [k][col]

    const int tid = threadIdx.x;
    const int tx  = tid & 15;       // col group: cols tx*4 + g*64 .. +3
    const int ty  = tid >> 4;       // row group: rows ty*4 .. +3
    const int r0  = blockIdx.x * 64;

    float acc[4][12];
    #pragma unroll
    for (int i = 0; i < 4; i++)
        #pragma unroll
        for (int s = 0; s < 12; s++) acc[i][s] = 0.f;

    for (int kk = 0; kk < D_IN; kk += 16) {
        // --- load x tile: 64 rows x 16 k, one float4 per thread ---
        {
            int row = tid >> 2;          // 0..63
            int seg = tid & 3;           // 0..3
            float4 v = *(const float4*)&x[(r0 + row) * D_IN + kk + seg * 4];
            xs[seg * 4 + 0][row] = v.x;
            xs[seg * 4 + 1][row] = v.y;
            xs[seg * 4 + 2][row] = v.z;
            xs[seg * 4 + 3][row] = v.w;
        }
        // --- load W tile: 192 cols x 16 k (768 float4, 3 per thread) ---
        #pragma unroll
        for (int t = 0; t < 3; t++) {
            int idx = tid + t * 256;     // 0..767
            int c   = idx >> 2;          // 0..191
            int seg = idx & 3;           // 0..3
            const float* Wsrc = (c < 64)  ? &Wq[c * D_IN]
                              : (c < 128) ? &Wk[(c - 64) * D_IN]
                                          : &Wv[(c - 128) * D_IN];
            float4 v = *(const float4*)&Wsrc[kk + seg * 4];
            ws[seg * 4 + 0][c] = v.x;
            ws[seg * 4 + 1][c] = v.y;
            ws[seg * 4 + 2][c] = v.z;
            ws[seg * 4 + 3][c] = v.w;
        }
        __syncthreads();

        #pragma unroll
        for (int k = 0; k < 16; k++) {
            float4 xv4 = *(const float4*)&xs[k][ty * 4];
            float xv[4] = {xv4.x, xv4.y, xv4.z, xv4.w};
            float wv[12];
            #pragma unroll
            for (int g = 0; g < 3; g++) {
                float4 w4 = *(const float4*)&ws[k][tx * 4 + g * 64];
                wv[g * 4 + 0] = w4.x; wv[g * 4 + 1] = w4.y;
                wv[g * 4 + 2] = w4.z; wv[g * 4 + 3] = w4.w;
            }
            #pragma unroll
            for (int i = 0; i < 4; i++)
                #pragma unroll
                for (int s = 0; s < 12; s++)
                    acc[i][s] += xv[i] * wv[s];
        }
        __syncthreads();
    }

    // --- epilogue: bias + vectorized scatter to g_Q / g_K / g_V ---
    #pragma unroll
    for (int g = 0; g < 3; g++) {
        float b[4];
        float* dst;
        int hc = tx * 4;                 // head column base (0..60)
        if (g == 0) {
            dst = g_Q;
            #pragma unroll
            for (int cc = 0; cc < 4; cc++) b[cc] = bq[hc + cc];
        } else if (g == 1) {
            dst = g_K;
            #pragma unroll
            for (int cc = 0; cc < 4; cc++) b[cc] = bk[hc + cc];
        } else {
            dst = g_V;
            #pragma unroll
            for (int cc = 0; cc < 4; cc++) b[cc] = 0.f;
        }
        #pragma unroll
        for (int i = 0; i < 4; i++) {
            int row = r0 + ty * 4 + i;
            float4 o;
            o.x = acc[i][g * 4 + 0] + b[0];
            o.y = acc[i][g * 4 + 1] + b[1];
            o.z = acc[i][g * 4 + 2] + b[2];
            o.w = acc[i][g * 4 + 3] + b[3];
            *(float4*)&dst[row * H_DIM + hc] = o;
        }
    }
}

// ---------------------------------------------------------------------------
// Kernel 2: sparse attention. One warp per node; lane l owns neighbor l.
// K rows staged into smem with row-coalesced loads (2 rows per LDG.128),
// then per-lane dot from conflict-free padded smem (stride 68: 68*l mod 32
// = 4l distinct per 8-lane LDS.128 phase).
// ---------------------------------------------------------------------------
#define ATT_WARPS 4

__global__ __launch_bounds__(ATT_WARPS * 32) void attn_kernel(
    const int*   __restrict__ edge_index,   // [2, E]: src then dst
    const int*   __restrict__ edge_type,    // [E]
    const float* __restrict__ ek_table,     // [16]
    float*       __restrict__ out)          // [N, 64]
{
    __shared__ __align__(16) float sK[ATT_WARPS][32][68];
    __shared__ int sJ[ATT_WARPS][32];

    const int w    = threadIdx.x >> 5;
    const int lane = threadIdx.x & 31;
    const int i    = blockIdx.x * ATT_WARPS + w;
    const int e    = i * DEG + lane;

    const int   j  = edge_index[E_EDGES + e];     // dst neighbor of node i
    const float ek = ek_table[edge_type[e]];
    sJ[w][lane] = j;
    __syncwarp();

    // --- stage K rows: 2 rows per iteration, fully coalesced ---
    const int half = lane >> 4;        // 0/1: which of the 2 rows
    const int q16  = lane & 15;        // float4 index within row
    #pragma unroll
    for (int rr = 0; rr < 16; rr++) {
        int r  = rr * 2 + half;
        int jr = sJ[w][r];
        float4 v = *(const float4*)&g_K[jr * H_DIM + q16 * 4];
        *(float4*)&sK[w][r][q16 * 4] = v;
    }
    __syncwarp();

    // --- dot(Q_i, K_{j_lane}) from smem ---
    const float4* Qi = (const float4*)&g_Q[i * H_DIM];
    float s = 0.f;
    #pragma unroll
    for (int d4 = 0; d4 < H_DIM / 4; d4++) {
        float4 q = Qi[d4];
        float4 k = *(const float4*)&sK[w][lane][d4 * 4];
        s += q.x * k.x + q.y * k.y + q.z * k.z + q.w * k.w;
    }
    s = (s + ek) * (1.0f / 512.0f);   // (/H) then (/sqrt(H)) = /512

    // --- warp softmax over the 32 neighbor scores ---
    float m = s;
    #pragma unroll
    for (int o = 16; o > 0; o >>= 1) m = fmaxf(m, __shfl_xor_sync(0xffffffffu, m, o));
    float p = __expf(s - m);
    float sum = p;
    #pragma unroll
    for (int o = 16; o > 0; o >>= 1) sum += __shfl_xor_sync(0xffffffffu, sum, o);
    p /= sum;

    // --- weighted V sum: lane owns output dims {2*lane, 2*lane+1} ---
    float a0 = 0.f, a1 = 0.f;
    #pragma unroll
    for (int n = 0; n < DEG; n++) {
        float pn = __shfl_sync(0xffffffffu, p, n);
        int   jn = sJ[w][n];
        float2 v = *(const float2*)&g_V[jn * H_DIM + lane * 2];
        a0 += pn * v.x;
        a1 += pn * v.y;
    }
    *(float2*)&out[i * H_DIM + lane * 2] = make_float2(a0, a1);
}

// ---------------------------------------------------------------------------
extern "C" void kernel_launch(void* const* d_in, const int* in_sizes, int n_in,
                              void* d_out, int out_size)
{
    const float* x          = (const float*)d_in[0];
    // d_in[1] = adj [8192*8192] — intentionally unused (edge list is exact)
    const int*   edge_index = (const int*)d_in[2];
    const int*   edge_type  = (const int*)d_in[3];
    const float* Wq         = (const float*)d_in[4];
    const float* bq         = (const float*)d_in[5];
    const float* Wk         = (const float*)d_in[6];
    const float* bk         = (const float*)d_in[7];
    const float* Wv         = (const float*)d_in[8];
    const float* ekt        = (const float*)d_in[9];
    float*       out        = (float*)d_out;

    qkv_kernel<<<N_NODES / 64, 256>>>(x, Wq, bq, Wk, bk, Wv);
    attn_kernel<<<N_NODES / ATT_WARPS, ATT_WARPS * 32>>>(edge_index, edge_type, ekt, out);
}

// round 3
// speedup vs baseline: 1.3253x; 1.1389x over previous
#include <cuda_runtime.h>

#define N_NODES 8192
#define D_IN    256
#define H_DIM   64
#define DEG     32
#define E_EDGES (N_NODES * DEG)

// Scratch for projected Q, K, V  (8192 x 64 floats each = 2 MB each)
__device__ float g_Q[N_NODES * H_DIM];
__device__ float g_K[N_NODES * H_DIM];
__device__ float g_V[N_NODES * H_DIM];

// ---------------------------------------------------------------------------
// Kernel 1: fused QKV projection.
//   C[8192, 192] = x[8192,256] @ [Wq;Wk;Wv]^T (+ bias for Q,K cols)
// Block tile: 64 rows x 192 cols, BK=16. 256 threads.
// Microtile 4 rows x 12 cols, cols owned as 3 float4 groups (vectorized LDS).
// ---------------------------------------------------------------------------
__global__ __launch_bounds__(256) void qkv_kernel(
    const float* __restrict__ x,
    const float* __restrict__ Wq, const float* __restrict__ bq,
    const float* __restrict__ Wk, const float* __restrict__ bk,
    const float* __restrict__ Wv)
{
    __shared__ __align__(16) float xs[16][68];    // [k][row]
    __shared__ __align__(16) float ws[16][196];   // [k][col]

    const int tid = threadIdx.x;
    const int tx  = tid & 15;       // col group: cols tx*4 + g*64 .. +3
    const int ty  = tid >> 4;       // row group: rows ty*4 .. +3
    const int r0  = blockIdx.x * 64;

    float acc[4][12];
    #pragma unroll
    for (int i = 0; i < 4; i++)
        #pragma unroll
        for (int s = 0; s < 12; s++) acc[i][s] = 0.f;

    for (int kk = 0; kk < D_IN; kk += 16) {
        // --- load x tile: 64 rows x 16 k, one float4 per thread ---
        {
            int row = tid >> 2;          // 0..63
            int seg = tid & 3;           // 0..3
            float4 v = *(const float4*)&x[(r0 + row) * D_IN + kk + seg * 4];
            xs[seg * 4 + 0][row] = v.x;
            xs[seg * 4 + 1][row] = v.y;
            xs[seg * 4 + 2][row] = v.z;
            xs[seg * 4 + 3][row] = v.w;
        }
        // --- load W tile: 192 cols x 16 k (768 float4, 3 per thread) ---
        #pragma unroll
        for (int t = 0; t < 3; t++) {
            int idx = tid + t * 256;     // 0..767
            int c   = idx >> 2;          // 0..191
            int seg = idx & 3;           // 0..3
            const float* Wsrc = (c < 64)  ? &Wq[c * D_IN]
                              : (c < 128) ? &Wk[(c - 64) * D_IN]
                                          : &Wv[(c - 128) * D_IN];
            float4 v = *(const float4*)&Wsrc[kk + seg * 4];
            ws[seg * 4 + 0][c] = v.x;
            ws[seg * 4 + 1][c] = v.y;
            ws[seg * 4 + 2][c] = v.z;
            ws[seg * 4 + 3][c] = v.w;
        }
        __syncthreads();

        #pragma unroll
        for (int k = 0; k < 16; k++) {
            float4 xv4 = *(const float4*)&xs[k][ty * 4];
            float xv[4] = {xv4.x, xv4.y, xv4.z, xv4.w};
            float wv[12];
            #pragma unroll
            for (int g = 0; g < 3; g++) {
                float4 w4 = *(const float4*)&ws[k][tx * 4 + g * 64];
                wv[g * 4 + 0] = w4.x; wv[g * 4 + 1] = w4.y;
                wv[g * 4 + 2] = w4.z; wv[g * 4 + 3] = w4.w;
            }
            #pragma unroll
            for (int i = 0; i < 4; i++)
                #pragma unroll
                for (int s = 0; s < 12; s++)
                    acc[i][s] += xv[i] * wv[s];
        }
        __syncthreads();
    }

    // --- epilogue: bias + vectorized scatter to g_Q / g_K / g_V ---
    #pragma unroll
    for (int g = 0; g < 3; g++) {
        float b[4];
        float* dst;
        int hc = tx * 4;                 // head column base (0..60)
        if (g == 0) {
            dst = g_Q;
            #pragma unroll
            for (int cc = 0; cc < 4; cc++) b[cc] = bq[hc + cc];
        } else if (g == 1) {
            dst = g_K;
            #pragma unroll
            for (int cc = 0; cc < 4; cc++) b[cc] = bk[hc + cc];
        } else {
            dst = g_V;
            #pragma unroll
            for (int cc = 0; cc < 4; cc++) b[cc] = 0.f;
        }
        #pragma unroll
        for (int i = 0; i < 4; i++) {
            int row = r0 + ty * 4 + i;
            float4 o;
            o.x = acc[i][g * 4 + 0] + b[0];
            o.y = acc[i][g * 4 + 1] + b[1];
            o.z = acc[i][g * 4 + 2] + b[2];
            o.w = acc[i][g * 4 + 3] + b[3];
            *(float4*)&dst[row * H_DIM + hc] = o;
        }
    }
}

// ---------------------------------------------------------------------------
// Kernel 2: sparse attention. One warp per node. No shared memory.
// Scores computed cooperatively: pass p handles neighbors 4p..4p+3;
// lane l loads K-dims (l>>2)*8..+7 of neighbor 4p+(l&3), partial dot
// reduced over lanes with shfl_xor(4,8,16). Lane l keeps pass l>>2's
// result == score of neighbor l. Then warp softmax + coalesced V gather.
// ---------------------------------------------------------------------------
#define ATT_WARPS 8

__global__ __launch_bounds__(ATT_WARPS * 32) void attn_kernel(
    const int*   __restrict__ edge_index,   // [2, E]: src then dst
    const int*   __restrict__ edge_type,    // [E]
    const float* __restrict__ ek_table,     // [16]
    float*       __restrict__ out)          // [N, 64]
{
    const int lane = threadIdx.x & 31;
    const int i    = blockIdx.x * ATT_WARPS + (threadIdx.x >> 5);
    const int e    = i * DEG + lane;

    const int   j  = edge_index[E_EDGES + e];     // dst neighbor of node i
    const float ek = ek_table[edge_type[e]];

    // This lane's Q chunk: dims dc..dc+7
    const int dc = (lane >> 2) * 8;
    const float4 q0 = *(const float4*)&g_Q[i * H_DIM + dc];
    const float4 q1 = *(const float4*)&g_Q[i * H_DIM + dc + 4];

    float s = 0.f;
    #pragma unroll
    for (int pass = 0; pass < 8; pass++) {
        const int n  = pass * 4 + (lane & 3);
        const int jn = __shfl_sync(0xffffffffu, j, n);
        const float4* Kp = (const float4*)&g_K[jn * H_DIM + dc];
        const float4 k0 = Kp[0];
        const float4 k1 = Kp[1];
        float part = q0.x * k0.x + q0.y * k0.y + q0.z * k0.z + q0.w * k0.w
                   + q1.x * k1.x + q1.y * k1.y + q1.z * k1.z + q1.w * k1.w;
        part += __shfl_xor_sync(0xffffffffu, part, 4);
        part += __shfl_xor_sync(0xffffffffu, part, 8);
        part += __shfl_xor_sync(0xffffffffu, part, 16);
        if (pass == (lane >> 2)) s = part;
    }
    s = (s + ek) * (1.0f / 512.0f);   // (/H) then (/sqrt(H)) = /512

    // --- warp softmax over the 32 neighbor scores ---
    float m = s;
    #pragma unroll
    for (int o = 16; o > 0; o >>= 1) m = fmaxf(m, __shfl_xor_sync(0xffffffffu, m, o));
    const float pexp = __expf(s - m);
    float sum = pexp;
    #pragma unroll
    for (int o = 16; o > 0; o >>= 1) sum += __shfl_xor_sync(0xffffffffu, sum, o);
    const float p = pexp / sum;

    // --- weighted V sum: lane owns output dims {2*lane, 2*lane+1} ---
    float a0 = 0.f, a1 = 0.f;
    #pragma unroll
    for (int n = 0; n < DEG; n++) {
        const float pn = __shfl_sync(0xffffffffu, p, n);
        const int   jn = __shfl_sync(0xffffffffu, j, n);
        const float2 v = *(const float2*)&g_V[jn * H_DIM + lane * 2];
        a0 += pn * v.x;
        a1 += pn * v.y;
    }
    *(float2*)&out[i * H_DIM + lane * 2] = make_float2(a0, a1);
}

// ---------------------------------------------------------------------------
extern "C" void kernel_launch(void* const* d_in, const int* in_sizes, int n_in,
                              void* d_out, int out_size)
{
    const float* x          = (const float*)d_in[0];
    // d_in[1] = adj [8192*8192] — intentionally unused (edge list is exact)
    const int*   edge_index = (const int*)d_in[2];
    const int*   edge_type  = (const int*)d_in[3];
    const float* Wq         = (const float*)d_in[4];
    const float* bq         = (const float*)d_in[5];
    const float* Wk         = (const float*)d_in[6];
    const float* bk         = (const float*)d_in[7];
    const float* Wv         = (const float*)d_in[8];
    const float* ekt        = (const float*)d_in[9];
    float*       out        = (float*)d_out;

    qkv_kernel<<<N_NODES / 64, 256>>>(x, Wq, bq, Wk, bk, Wv);
    attn_kernel<<<N_NODES / ATT_WARPS, ATT_WARPS * 32>>>(edge_index, edge_type, ekt, out);
}

// round 5
// speedup vs baseline: 1.6437x; 1.2403x over previous
#include <cuda_runtime.h>
#include <cuda_bf16.h>
#include <cstdint>

#define N_NODES 8192
#define D_IN    256
#define H_DIM   64
#define DEG     32
#define E_EDGES (N_NODES * DEG)

// Scratch: projected Q, K, V (fp32) + bf16 hi/lo splits of x and W
__device__ float g_Q[N_NODES * H_DIM];
__device__ float g_K[N_NODES * H_DIM];
__device__ float g_V[N_NODES * H_DIM];
__device__ __nv_bfloat16 g_xh[N_NODES * D_IN];
__device__ __nv_bfloat16 g_xl[N_NODES * D_IN];
__device__ __nv_bfloat16 g_Wh[192 * D_IN];
__device__ __nv_bfloat16 g_Wl[192 * D_IN];

// ===========================================================================
// helpers (all plain sm_80-era PTX — no 'a'-gated features)
// ===========================================================================
__device__ __forceinline__ uint32_t smem_u32(const void* p) {
    uint32_t a;
    asm("{ .reg .u64 t; cvta.to.shared.u64 t, %1; cvt.u32.u64 %0, t; }"
        : "=r"(a) : "l"(p));
    return a;
}
__device__ __forceinline__ void cp_async16(uint32_t dst, const void* src) {
    asm volatile("cp.async.cg.shared.global [%0], [%1], 16;"
                 :: "r"(dst), "l"(src) : "memory");
}
__device__ __forceinline__ void ldmatrix_x4(uint32_t* r, uint32_t addr) {
    asm volatile("ldmatrix.sync.aligned.m8n8.x4.shared.b16 {%0,%1,%2,%3}, [%4];"
                 : "=r"(r[0]), "=r"(r[1]), "=r"(r[2]), "=r"(r[3]) : "r"(addr));
}
__device__ __forceinline__ void mma_bf16(float* c, const uint32_t* a, const uint32_t* b) {
    asm volatile(
        "mma.sync.aligned.m16n8k16.row.col.f32.bf16.bf16.f32 "
        "{%0,%1,%2,%3}, {%4,%5,%6,%7}, {%8,%9}, {%0,%1,%2,%3};"
        : "+f"(c[0]), "+f"(c[1]), "+f"(c[2]), "+f"(c[3])
        : "r"(a[0]), "r"(a[1]), "r"(a[2]), "r"(a[3]), "r"(b[0]), "r"(b[1]));
}

// ===========================================================================
// Kernel 0: split fp32 x / W into bf16 hi + lo.
// ===========================================================================
__device__ __forceinline__ void split_store4(__nv_bfloat16* hi, __nv_bfloat16* lo,
                                             float4 v) {
    float f[4] = {v.x, v.y, v.z, v.w};
    unsigned short hu[4], lu[4];
    #pragma unroll
    for (int i = 0; i < 4; i++) {
        __nv_bfloat16 hb = __float2bfloat16(f[i]);
        __nv_bfloat16 lb = __float2bfloat16(f[i] - __bfloat162float(hb));
        hu[i] = __bfloat16_as_ushort(hb);
        lu[i] = __bfloat16_as_ushort(lb);
    }
    uint2 hv = make_uint2((uint32_t)hu[0] | ((uint32_t)hu[1] << 16),
                          (uint32_t)hu[2] | ((uint32_t)hu[3] << 16));
    uint2 lv = make_uint2((uint32_t)lu[0] | ((uint32_t)lu[1] << 16),
                          (uint32_t)lu[2] | ((uint32_t)lu[3] << 16));
    *(uint2*)hi = hv;
    *(uint2*)lo = lv;
}

__global__ __launch_bounds__(256) void convert_kernel(
    const float* __restrict__ x,
    const float* __restrict__ Wq, const float* __restrict__ Wk,
    const float* __restrict__ Wv)
{
    const int tid = threadIdx.x;
    if (blockIdx.x < 2048) {
        int idx = blockIdx.x * 256 + tid;           // float4 index into x
        float4 v = ((const float4*)x)[idx];
        split_store4(&g_xh[idx * 4], &g_xl[idx * 4], v);
    } else {
        int w = (blockIdx.x - 2048) * 256 + tid;    // 0..12287
        int base = w * 4;
        int row = base >> 8;
        int c   = base & 255;
        const float* src = (row < 64)  ? &Wq[row * D_IN + c]
                         : (row < 128) ? &Wk[(row - 64) * D_IN + c]
                                       : &Wv[(row - 128) * D_IN + c];
        float4 v = *(const float4*)src;
        split_store4(&g_Wh[base], &g_Wl[base], v);
    }
}

// ===========================================================================
// Kernel 1: QKV projection, bf16-split GEMM via mma.sync (m16n8k16).
//   C[8192,192] = x @ [Wq;Wk;Wv]^T, 3 passes: (xh,Wh), (xh,Wl), (xl,Wh).
// CTA: 64 rows x 192 cols, 256 threads. Warp tile 32x48 (2x6 mma tiles).
// K chunks of 64, cp.async double buffer, padded smem (144B rows).
// ===========================================================================
#define LDS_B     144              // padded row stride in bytes (72 bf16)
#define A_BYTES   (64 * LDS_B)     // 9216
#define B_BYTES   (192 * LDS_B)    // 27648
#define STAGE_B   (A_BYTES + B_BYTES)
#define QKV_SMEM  (2 * STAGE_B)    // 73728

__device__ __forceinline__ void qkv_issue_loads(
    int it, uint32_t sbase, int r0, int tid)
{
    const int pass = it >> 2;
    const int kk   = (it & 3) * 64;
    const __nv_bfloat16* A = (pass == 2) ? g_xl : g_xh;
    const __nv_bfloat16* B = (pass == 1) ? g_Wl : g_Wh;
    const uint32_t sa = sbase + (uint32_t)(it & 1) * STAGE_B;
    const uint32_t sb = sa + A_BYTES;
    #pragma unroll
    for (int t = 0; t < 2; t++) {                  // A: 512 x 16B
        int idx = tid + t * 256;
        int row = idx >> 3, c = idx & 7;
        cp_async16(sa + row * LDS_B + c * 16, A + (r0 + row) * D_IN + kk + c * 8);
    }
    #pragma unroll
    for (int t = 0; t < 6; t++) {                  // B: 1536 x 16B
        int idx = tid + t * 256;
        int row = idx >> 3, c = idx & 7;
        cp_async16(sb + row * LDS_B + c * 16, B + row * D_IN + kk + c * 8);
    }
    asm volatile("cp.async.commit_group;" ::: "memory");
}

__global__ __launch_bounds__(256) void qkv_mma_kernel(
    const float* __restrict__ bq, const float* __restrict__ bk)
{
    extern __shared__ __align__(16) char sm[];
    const int tid  = threadIdx.x;
    const int lane = tid & 31;
    const int wid  = tid >> 5;
    const int wm   = wid & 1;       // 2 M sub-tiles of 32
    const int wn   = wid >> 1;      // 4 N sub-tiles of 48
    const int r0   = blockIdx.x * 64;
    const uint32_t sbase = smem_u32(sm);

    float acc[2][6][4];
    #pragma unroll
    for (int mt = 0; mt < 2; mt++)
        #pragma unroll
        for (int nt = 0; nt < 6; nt++)
            #pragma unroll
            for (int q = 0; q < 4; q++) acc[mt][nt][q] = 0.f;

    qkv_issue_loads(0, sbase, r0, tid);

    #pragma unroll 1
    for (int it = 0; it < 12; it++) {
        if (it + 1 < 12) {
            qkv_issue_loads(it + 1, sbase, r0, tid);
            asm volatile("cp.async.wait_group 1;" ::: "memory");
        } else {
            asm volatile("cp.async.wait_group 0;" ::: "memory");
        }
        __syncthreads();

        const uint32_t sa = sbase + (uint32_t)(it & 1) * STAGE_B;
        const uint32_t sb = sa + A_BYTES;
        #pragma unroll
        for (int ks = 0; ks < 4; ks++) {
            const int kb = ks * 16;
            uint32_t af[2][4];
            #pragma unroll
            for (int mt = 0; mt < 2; mt++) {
                int row = wm * 32 + mt * 16 + (lane & 15);
                uint32_t addr = sa + row * LDS_B + (kb + (lane >> 4) * 8) * 2;
                ldmatrix_x4(af[mt], addr);
            }
            uint32_t bfr[6][2];
            #pragma unroll
            for (int np = 0; np < 3; np++) {       // 2 n-tiles per ldmatrix.x4
                int row = wn * 48 + np * 16 + (lane >> 4) * 8 + (lane & 7);
                uint32_t addr = sb + row * LDS_B + (kb + ((lane >> 3) & 1) * 8) * 2;
                uint32_t r[4];
                ldmatrix_x4(r, addr);
                bfr[np * 2][0] = r[0]; bfr[np * 2][1] = r[1];
                bfr[np * 2 + 1][0] = r[2]; bfr[np * 2 + 1][1] = r[3];
            }
            #pragma unroll
            for (int mt = 0; mt < 2; mt++)
                #pragma unroll
                for (int nt = 0; nt < 6; nt++)
                    mma_bf16(acc[mt][nt], af[mt], bfr[nt]);
        }
        __syncthreads();
    }

    // epilogue: fragment -> g_Q / g_K / g_V with bias
    const int grp = lane >> 2;
    const int qid = lane & 3;
    #pragma unroll
    for (int mt = 0; mt < 2; mt++) {
        int row0 = r0 + wm * 32 + mt * 16 + grp;
        #pragma unroll
        for (int nt = 0; nt < 6; nt++) {
            int cb  = wn * 48 + nt * 8;
            int h   = cb >> 6;
            int hc0 = (cb & 63) + qid * 2;
            float* dst;
            float b0, b1;
            if (h == 0)      { dst = g_Q; b0 = bq[hc0]; b1 = bq[hc0 + 1]; }
            else if (h == 1) { dst = g_K; b0 = bk[hc0]; b1 = bk[hc0 + 1]; }
            else             { dst = g_V; b0 = 0.f;     b1 = 0.f; }
            *(float2*)&dst[row0 * H_DIM + hc0] =
                make_float2(acc[mt][nt][0] + b0, acc[mt][nt][1] + b1);
            *(float2*)&dst[(row0 + 8) * H_DIM + hc0] =
                make_float2(acc[mt][nt][2] + b0, acc[mt][nt][3] + b1);
        }
    }
}

// ---------------------------------------------------------------------------
// Kernel 2: sparse attention. One warp per node. No shared memory.
// (unchanged from round 3 — 17.6us, next round's target)
// ---------------------------------------------------------------------------
#define ATT_WARPS 8

__global__ __launch_bounds__(ATT_WARPS * 32) void attn_kernel(
    const int*   __restrict__ edge_index,   // [2, E]: src then dst
    const int*   __restrict__ edge_type,    // [E]
    const float* __restrict__ ek_table,     // [16]
    float*       __restrict__ out)          // [N, 64]
{
    const int lane = threadIdx.x & 31;
    const int i    = blockIdx.x * ATT_WARPS + (threadIdx.x >> 5);
    const int e    = i * DEG + lane;

    const int   j  = edge_index[E_EDGES + e];     // dst neighbor of node i
    const float ek = ek_table[edge_type[e]];

    const int dc = (lane >> 2) * 8;
    const float4 q0 = *(const float4*)&g_Q[i * H_DIM + dc];
    const float4 q1 = *(const float4*)&g_Q[i * H_DIM + dc + 4];

    float s = 0.f;
    #pragma unroll
    for (int pass = 0; pass < 8; pass++) {
        const int n  = pass * 4 + (lane & 3);
        const int jn = __shfl_sync(0xffffffffu, j, n);
        const float4* Kp = (const float4*)&g_K[jn * H_DIM + dc];
        const float4 k0 = Kp[0];
        const float4 k1 = Kp[1];
        float part = q0.x * k0.x + q0.y * k0.y + q0.z * k0.z + q0.w * k0.w
                   + q1.x * k1.x + q1.y * k1.y + q1.z * k1.z + q1.w * k1.w;
        part += __shfl_xor_sync(0xffffffffu, part, 4);
        part += __shfl_xor_sync(0xffffffffu, part, 8);
        part += __shfl_xor_sync(0xffffffffu, part, 16);
        if (pass == (lane >> 2)) s = part;
    }
    s = (s + ek) * (1.0f / 512.0f);

    float m = s;
    #pragma unroll
    for (int o = 16; o > 0; o >>= 1) m = fmaxf(m, __shfl_xor_sync(0xffffffffu, m, o));
    const float pexp = __expf(s - m);
    float sum = pexp;
    #pragma unroll
    for (int o = 16; o > 0; o >>= 1) sum += __shfl_xor_sync(0xffffffffu, sum, o);
    const float p = pexp / sum;

    float a0 = 0.f, a1 = 0.f;
    #pragma unroll
    for (int n = 0; n < DEG; n++) {
        const float pn = __shfl_sync(0xffffffffu, p, n);
        const int   jn = __shfl_sync(0xffffffffu, j, n);
        const float2 v = *(const float2*)&g_V[jn * H_DIM + lane * 2];
        a0 += pn * v.x;
        a1 += pn * v.y;
    }
    *(float2*)&out[i * H_DIM + lane * 2] = make_float2(a0, a1);
}

// ---------------------------------------------------------------------------
extern "C" void kernel_launch(void* const* d_in, const int* in_sizes, int n_in,
                              void* d_out, int out_size)
{
    const float* x          = (const float*)d_in[0];
    // d_in[1] = adj — intentionally unused (edge list is exact)
    const int*   edge_index = (const int*)d_in[2];
    const int*   edge_type  = (const int*)d_in[3];
    const float* Wq         = (const float*)d_in[4];
    const float* bq         = (const float*)d_in[5];
    const float* Wk         = (const float*)d_in[6];
    const float* bk         = (const float*)d_in[7];
    const float* Wv         = (const float*)d_in[8];
    const float* ekt        = (const float*)d_in[9];
    float*       out        = (float*)d_out;

    static bool attr_set = false;
    if (!attr_set) {
        cudaFuncSetAttribute(qkv_mma_kernel,
                             cudaFuncAttributeMaxDynamicSharedMemorySize, QKV_SMEM);
        attr_set = true;
    }

    convert_kernel<<<2096, 256>>>(x, Wq, Wk, Wv);
    qkv_mma_kernel<<<N_NODES / 64, 256, QKV_SMEM>>>(bq, bk);
    attn_kernel<<<N_NODES / ATT_WARPS, ATT_WARPS * 32>>>(edge_index, edge_type, ekt, out);
}